// round 2
// baseline (speedup 1.0000x reference)
#include <cuda_runtime.h>
#include <cuda_bf16.h>
#include <math.h>

// ---------------------------------------------------------------------------
// IPMTrans: 3-scale BEV transform
//   per scale: v[b, c*Y+y, zx] = max_{s<4}( valid ? bilinear(feat[b*4+s,c], coord) : 0 )
//              bev[b,o,zx]    = silu( sum_i w[o,i]*v[b,i,zx] + bias[o] )
//   mask[b,n] = max_s valid(scale2 coords)
// Output concat: bev2 (2,256,4096) | bev4 (2,512,1024) | bev8 (2,1024,256) | mask (2,16384)
// ---------------------------------------------------------------------------

#define BVAL 2
#define SVAL 4
#define YVAL 4

// scratch for the max-pooled sampled features (GEMM inputs)
__device__ float g_v2[2ULL * 1024 * 4096];   // (B, 256*Y, 64*64)
__device__ float g_v4[2ULL * 2048 * 1024];   // (B, 512*Y, 32*32)
__device__ float g_v8[2ULL * 4096 * 256];    // (B, 1024*Y, 16*16)

// ---------------------------------------------------------------------------
// Kernel 1: bilinear sample + mask + max over S.
// grid = (C, B). Each block owns one (b, c) pair; loops over Y*ZX outputs.
// Working set: 4 channel planes (one per s) = 4*H*W*4 bytes <= 64KB -> L1.
// ---------------------------------------------------------------------------
__global__ void sample_max_kernel(const float* __restrict__ feat,
                                  const float* __restrict__ coords,
                                  float* __restrict__ v,
                                  int C, int Wd, int ZX)
{
    const int c = blockIdx.x;
    const int b = blockIdx.y;
    const int HW = Wd * Wd;
    const int N = YVAL * ZX;
    const float sc = 0.5f * (float)(Wd - 1);

    const float2* __restrict__ crd = (const float2*)coords;

    // per-(b,c) plane base pointers for the 4 sweeps
    const float* __restrict__ p0 = feat + ((size_t)(b * SVAL + 0) * C + c) * HW;
    const float* __restrict__ p1 = feat + ((size_t)(b * SVAL + 1) * C + c) * HW;
    const float* __restrict__ p2 = feat + ((size_t)(b * SVAL + 2) * C + c) * HW;
    const float* __restrict__ p3 = feat + ((size_t)(b * SVAL + 3) * C + c) * HW;
    const float* planes[SVAL] = {p0, p1, p2, p3};

    float* __restrict__ vout = v + ((size_t)(b * C + c) * YVAL) * (size_t)ZX;

    for (int idx = threadIdx.x; idx < N; idx += blockDim.x) {
        float vmax = -INFINITY;
#pragma unroll
        for (int s = 0; s < SVAL; s++) {
            const int bs = b * SVAL + s;
            float2 g = crd[(size_t)bs * N + idx];

            float ix = (g.x + 1.0f) * sc;
            float iy = (g.y + 1.0f) * sc;
            float x0f = floorf(ix);
            float y0f = floorf(iy);
            float wx = ix - x0f;
            float wy = iy - y0f;
            int x0 = (int)x0f;
            int y0 = (int)y0f;
            x0 = min(max(x0, 0), Wd - 1);
            y0 = min(max(y0, 0), Wd - 1);
            int x1 = min(x0 + 1, Wd - 1);
            int y1 = min(y0 + 1, Wd - 1);

            const float* pl = planes[s];
            float v00 = pl[y0 * Wd + x0];
            float v01 = pl[y0 * Wd + x1];
            float v10 = pl[y1 * Wd + x0];
            float v11 = pl[y1 * Wd + x1];

            float samp = v00 * (1.0f - wx) * (1.0f - wy)
                       + v01 * wx * (1.0f - wy)
                       + v10 * (1.0f - wx) * wy
                       + v11 * wx * wy;

            bool valid = (g.x >= -1.0f) & (g.x <= 1.0f) & (g.y >= -1.0f) & (g.y <= 1.0f);
            float val = valid ? samp : 0.0f;
            vmax = fmaxf(vmax, val);
        }
        vout[idx] = vmax;
    }
}

// ---------------------------------------------------------------------------
// Kernel 2: batched fp32 GEMM + bias + silu.
//   out[z, m, n] = silu( bias[m] + sum_k W[m,k] * V[z,k,n] )
// BM=BN=64, BK=16, 256 threads, 4x4 per-thread microtile.
// ---------------------------------------------------------------------------
#define BM 64
#define BN 64
#define BK 16

__global__ __launch_bounds__(256) void gemm_bias_silu_kernel(
    const float* __restrict__ Wm, const float* __restrict__ V,
    const float* __restrict__ bias, float* __restrict__ out,
    int M, int N, int K)
{
    __shared__ float As[BK][BM];      // W tile, transposed: As[k][m]
    __shared__ float Bs[BK][BN];      // V tile: Bs[k][n]

    const int bn = blockIdx.x * BN;
    const int bm = blockIdx.y * BM;
    const int z  = blockIdx.z;

    const float* __restrict__ Vb = V + (size_t)z * K * N;
    float* __restrict__ outb = out + (size_t)z * M * N;

    const int tid = threadIdx.x;
    const int tx = tid & 15;          // 0..15 -> n
    const int ty = tid >> 4;          // 0..15 -> m

    float acc[4][4];
#pragma unroll
    for (int i = 0; i < 4; i++)
#pragma unroll
        for (int j = 0; j < 4; j++) acc[i][j] = 0.0f;

    for (int k0 = 0; k0 < K; k0 += BK) {
        // load W tile (BM x BK): each thread one float4 along k
        {
            int r = tid >> 2;                 // 0..63 (m)
            int cc = (tid & 3) * 4;           // 0,4,8,12 (k)
            float4 t = *(const float4*)&Wm[(size_t)(bm + r) * K + k0 + cc];
            As[cc + 0][r] = t.x;
            As[cc + 1][r] = t.y;
            As[cc + 2][r] = t.z;
            As[cc + 3][r] = t.w;
        }
        // load V tile (BK x BN): 1024 elems, 4 per thread, coalesced on n
#pragma unroll
        for (int j = 0; j < 4; j++) {
            int e = tid + j * 256;
            int r = e >> 6;                   // k
            int cc = e & 63;                  // n
            Bs[r][cc] = Vb[(size_t)(k0 + r) * N + bn + cc];
        }
        __syncthreads();

#pragma unroll
        for (int kk = 0; kk < BK; kk++) {
            float4 a4 = *(const float4*)&As[kk][ty * 4];
            float4 b4 = *(const float4*)&Bs[kk][tx * 4];
            float av[4] = {a4.x, a4.y, a4.z, a4.w};
            float bv[4] = {b4.x, b4.y, b4.z, b4.w};
#pragma unroll
            for (int i = 0; i < 4; i++)
#pragma unroll
                for (int j = 0; j < 4; j++)
                    acc[i][j] = fmaf(av[i], bv[j], acc[i][j]);
        }
        __syncthreads();
    }

    // epilogue: bias + silu
#pragma unroll
    for (int i = 0; i < 4; i++) {
        int m = bm + ty * 4 + i;
        float bs = bias[m];
#pragma unroll
        for (int j = 0; j < 4; j++) {
            int n = bn + tx * 4 + j;
            float x = acc[i][j] + bs;
            float s = x / (1.0f + expf(-x));
            outb[(size_t)m * N + n] = s;
        }
    }
}

// ---------------------------------------------------------------------------
// Kernel 3: valid voxel mask from scale-2 coords. out[b,n] = any_s valid
// ---------------------------------------------------------------------------
__global__ void mask_kernel(const float* __restrict__ coords,
                            float* __restrict__ out, int N)
{
    int i = blockIdx.x * blockDim.x + threadIdx.x;
    if (i >= BVAL * N) return;
    int b = i / N;
    int n = i % N;
    const float2* __restrict__ crd = (const float2*)coords;
    float m = 0.0f;
#pragma unroll
    for (int s = 0; s < SVAL; s++) {
        float2 g = crd[(size_t)(b * SVAL + s) * N + n];
        bool valid = (g.x >= -1.0f) & (g.x <= 1.0f) & (g.y >= -1.0f) & (g.y <= 1.0f);
        if (valid) m = 1.0f;
    }
    out[i] = m;
}

// ---------------------------------------------------------------------------
// launch
// ---------------------------------------------------------------------------
extern "C" void kernel_launch(void* const* d_in, const int* in_sizes, int n_in,
                              void* d_out, int out_size)
{
    const float* x3 = (const float*)d_in[0];
    const float* x4 = (const float*)d_in[1];
    const float* x5 = (const float*)d_in[2];
    const float* c2 = (const float*)d_in[3];
    const float* c4 = (const float*)d_in[4];
    const float* c8 = (const float*)d_in[5];
    const float* w2 = (const float*)d_in[6];
    const float* b2 = (const float*)d_in[7];
    const float* w4 = (const float*)d_in[8];
    const float* b4 = (const float*)d_in[9];
    const float* w8 = (const float*)d_in[10];
    const float* b8 = (const float*)d_in[11];

    float* out = (float*)d_out;

    float *v2, *v4, *v8;
    cudaGetSymbolAddress((void**)&v2, g_v2);
    cudaGetSymbolAddress((void**)&v4, g_v4);
    cudaGetSymbolAddress((void**)&v8, g_v8);

    // output layout offsets
    const size_t off_bev2 = 0;
    const size_t off_bev4 = off_bev2 + 2ULL * 256 * 4096;   // 2,097,152
    const size_t off_bev8 = off_bev4 + 2ULL * 512 * 1024;   // 3,145,728
    const size_t off_mask = off_bev8 + 2ULL * 1024 * 256;   // 3,670,016

    // ---- scale 2: C=256, H=W=64, ZX=4096, K=1024, M=256, N=4096 ----
    sample_max_kernel<<<dim3(256, BVAL), 256>>>(x3, c2, v2, 256, 64, 4096);
    gemm_bias_silu_kernel<<<dim3(4096 / BN, 256 / BM, BVAL), 256>>>(
        w2, v2, b2, out + off_bev2, 256, 4096, 1024);

    // ---- scale 4: C=512, H=W=32, ZX=1024, K=2048, M=512, N=1024 ----
    sample_max_kernel<<<dim3(512, BVAL), 256>>>(x4, c4, v4, 512, 32, 1024);
    gemm_bias_silu_kernel<<<dim3(1024 / BN, 512 / BM, BVAL), 256>>>(
        w4, v4, b4, out + off_bev4, 512, 1024, 2048);

    // ---- scale 8: C=1024, H=W=16, ZX=256, K=4096, M=1024, N=256 ----
    sample_max_kernel<<<dim3(1024, BVAL), 256>>>(x5, c8, v8, 1024, 16, 256);
    gemm_bias_silu_kernel<<<dim3(256 / BN, 1024 / BM, BVAL), 256>>>(
        w8, v8, b8, out + off_bev8, 1024, 256, 4096);

    // ---- valid voxel mask (scale-2 coords only), N = 4*64*64 = 16384 ----
    mask_kernel<<<(BVAL * 16384 + 255) / 256, 256>>>(c2, out + off_mask, 16384);
}

// round 3
// speedup vs baseline: 1.0001x; 1.0001x over previous
#include <cuda_runtime.h>
#include <cuda_bf16.h>
#include <math.h>

// ---------------------------------------------------------------------------
// IPMTrans: 3-scale BEV transform
//   per scale: v[b, c*Y+y, zx] = max_{s<4}( valid ? bilinear(feat[b*4+s,c], coord) : 0 )
//              bev[b,o,zx]    = silu( sum_i w[o,i]*v[b,i,zx] + bias[o] )
//   mask[b,n] = max_s valid(scale2 coords)
// Output concat: bev2 (2,256,4096) | bev4 (2,512,1024) | bev8 (2,1024,256) | mask (2,16384)
// ---------------------------------------------------------------------------

#define BVAL 2
#define SVAL 4
#define YVAL 4

// scratch for the max-pooled sampled features (GEMM inputs)
__device__ float g_v2[2ULL * 1024 * 4096];   // (B, 256*Y, 64*64)
__device__ float g_v4[2ULL * 2048 * 1024];   // (B, 512*Y, 32*32)
__device__ float g_v8[2ULL * 4096 * 256];    // (B, 1024*Y, 16*16)

// ---------------------------------------------------------------------------
// Kernel 1: bilinear sample + mask + max over S.
// grid = (C, B). Each block owns one (b, c) pair; loops over Y*ZX outputs.
// Working set: 4 channel planes (one per s) = 4*H*W*4 bytes <= 64KB -> L1.
// ---------------------------------------------------------------------------
__global__ void sample_max_kernel(const float* __restrict__ feat,
                                  const float* __restrict__ coords,
                                  float* __restrict__ v,
                                  int C, int Wd, int ZX)
{
    const int c = blockIdx.x;
    const int b = blockIdx.y;
    const int HW = Wd * Wd;
    const int N = YVAL * ZX;
    const float sc = 0.5f * (float)(Wd - 1);

    const float2* __restrict__ crd = (const float2*)coords;

    // per-(b,c) plane base pointers for the 4 sweeps
    const float* __restrict__ p0 = feat + ((size_t)(b * SVAL + 0) * C + c) * HW;
    const float* __restrict__ p1 = feat + ((size_t)(b * SVAL + 1) * C + c) * HW;
    const float* __restrict__ p2 = feat + ((size_t)(b * SVAL + 2) * C + c) * HW;
    const float* __restrict__ p3 = feat + ((size_t)(b * SVAL + 3) * C + c) * HW;
    const float* planes[SVAL] = {p0, p1, p2, p3};

    float* __restrict__ vout = v + ((size_t)(b * C + c) * YVAL) * (size_t)ZX;

    for (int idx = threadIdx.x; idx < N; idx += blockDim.x) {
        float vmax = -INFINITY;
#pragma unroll
        for (int s = 0; s < SVAL; s++) {
            const int bs = b * SVAL + s;
            float2 g = crd[(size_t)bs * N + idx];

            float ix = (g.x + 1.0f) * sc;
            float iy = (g.y + 1.0f) * sc;
            float x0f = floorf(ix);
            float y0f = floorf(iy);
            float wx = ix - x0f;
            float wy = iy - y0f;
            int x0 = (int)x0f;
            int y0 = (int)y0f;
            x0 = min(max(x0, 0), Wd - 1);
            y0 = min(max(y0, 0), Wd - 1);
            int x1 = min(x0 + 1, Wd - 1);
            int y1 = min(y0 + 1, Wd - 1);

            const float* pl = planes[s];
            float v00 = pl[y0 * Wd + x0];
            float v01 = pl[y0 * Wd + x1];
            float v10 = pl[y1 * Wd + x0];
            float v11 = pl[y1 * Wd + x1];

            float samp = v00 * (1.0f - wx) * (1.0f - wy)
                       + v01 * wx * (1.0f - wy)
                       + v10 * (1.0f - wx) * wy
                       + v11 * wx * wy;

            bool valid = (g.x >= -1.0f) & (g.x <= 1.0f) & (g.y >= -1.0f) & (g.y <= 1.0f);
            float val = valid ? samp : 0.0f;
            vmax = fmaxf(vmax, val);
        }
        vout[idx] = vmax;
    }
}

// ---------------------------------------------------------------------------
// Kernel 2: batched fp32 GEMM + bias + silu.
//   out[z, m, n] = silu( bias[m] + sum_k W[m,k] * V[z,k,n] )
// BM=BN=64, BK=16, 256 threads, 4x4 per-thread microtile.
// ---------------------------------------------------------------------------
#define BM 64
#define BN 64
#define BK 16

__global__ __launch_bounds__(256) void gemm_bias_silu_kernel(
    const float* __restrict__ Wm, const float* __restrict__ V,
    const float* __restrict__ bias, float* __restrict__ out,
    int M, int N, int K)
{
    __shared__ float As[BK][BM];      // W tile, transposed: As[k][m]
    __shared__ float Bs[BK][BN];      // V tile: Bs[k][n]

    const int bn = blockIdx.x * BN;
    const int bm = blockIdx.y * BM;
    const int z  = blockIdx.z;

    const float* __restrict__ Vb = V + (size_t)z * K * N;
    float* __restrict__ outb = out + (size_t)z * M * N;

    const int tid = threadIdx.x;
    const int tx = tid & 15;          // 0..15 -> n
    const int ty = tid >> 4;          // 0..15 -> m

    float acc[4][4];
#pragma unroll
    for (int i = 0; i < 4; i++)
#pragma unroll
        for (int j = 0; j < 4; j++) acc[i][j] = 0.0f;

    for (int k0 = 0; k0 < K; k0 += BK) {
        // load W tile (BM x BK): each thread one float4 along k
        {
            int r = tid >> 2;                 // 0..63 (m)
            int cc = (tid & 3) * 4;           // 0,4,8,12 (k)
            float4 t = *(const float4*)&Wm[(size_t)(bm + r) * K + k0 + cc];
            As[cc + 0][r] = t.x;
            As[cc + 1][r] = t.y;
            As[cc + 2][r] = t.z;
            As[cc + 3][r] = t.w;
        }
        // load V tile (BK x BN): 1024 elems, 4 per thread, coalesced on n
#pragma unroll
        for (int j = 0; j < 4; j++) {
            int e = tid + j * 256;
            int r = e >> 6;                   // k
            int cc = e & 63;                  // n
            Bs[r][cc] = Vb[(size_t)(k0 + r) * N + bn + cc];
        }
        __syncthreads();

#pragma unroll
        for (int kk = 0; kk < BK; kk++) {
            float4 a4 = *(const float4*)&As[kk][ty * 4];
            float4 b4 = *(const float4*)&Bs[kk][tx * 4];
            float av[4] = {a4.x, a4.y, a4.z, a4.w};
            float bv[4] = {b4.x, b4.y, b4.z, b4.w};
#pragma unroll
            for (int i = 0; i < 4; i++)
#pragma unroll
                for (int j = 0; j < 4; j++)
                    acc[i][j] = fmaf(av[i], bv[j], acc[i][j]);
        }
        __syncthreads();
    }

    // epilogue: bias + silu
#pragma unroll
    for (int i = 0; i < 4; i++) {
        int m = bm + ty * 4 + i;
        float bs = bias[m];
#pragma unroll
        for (int j = 0; j < 4; j++) {
            int n = bn + tx * 4 + j;
            float x = acc[i][j] + bs;
            float s = x / (1.0f + expf(-x));
            outb[(size_t)m * N + n] = s;
        }
    }
}

// ---------------------------------------------------------------------------
// Kernel 3: valid voxel mask from scale-2 coords. out[b,n] = any_s valid
// ---------------------------------------------------------------------------
__global__ void mask_kernel(const float* __restrict__ coords,
                            float* __restrict__ out, int N)
{
    int i = blockIdx.x * blockDim.x + threadIdx.x;
    if (i >= BVAL * N) return;
    int b = i / N;
    int n = i % N;
    const float2* __restrict__ crd = (const float2*)coords;
    float m = 0.0f;
#pragma unroll
    for (int s = 0; s < SVAL; s++) {
        float2 g = crd[(size_t)(b * SVAL + s) * N + n];
        bool valid = (g.x >= -1.0f) & (g.x <= 1.0f) & (g.y >= -1.0f) & (g.y <= 1.0f);
        if (valid) m = 1.0f;
    }
    out[i] = m;
}

// ---------------------------------------------------------------------------
// launch
// ---------------------------------------------------------------------------
extern "C" void kernel_launch(void* const* d_in, const int* in_sizes, int n_in,
                              void* d_out, int out_size)
{
    const float* x3 = (const float*)d_in[0];
    const float* x4 = (const float*)d_in[1];
    const float* x5 = (const float*)d_in[2];
    const float* c2 = (const float*)d_in[3];
    const float* c4 = (const float*)d_in[4];
    const float* c8 = (const float*)d_in[5];
    const float* w2 = (const float*)d_in[6];
    const float* b2 = (const float*)d_in[7];
    const float* w4 = (const float*)d_in[8];
    const float* b4 = (const float*)d_in[9];
    const float* w8 = (const float*)d_in[10];
    const float* b8 = (const float*)d_in[11];

    float* out = (float*)d_out;

    float *v2, *v4, *v8;
    cudaGetSymbolAddress((void**)&v2, g_v2);
    cudaGetSymbolAddress((void**)&v4, g_v4);
    cudaGetSymbolAddress((void**)&v8, g_v8);

    // output layout offsets
    const size_t off_bev2 = 0;
    const size_t off_bev4 = off_bev2 + 2ULL * 256 * 4096;   // 2,097,152
    const size_t off_bev8 = off_bev4 + 2ULL * 512 * 1024;   // 3,145,728
    const size_t off_mask = off_bev8 + 2ULL * 1024 * 256;   // 3,670,016

    // ---- scale 2: C=256, H=W=64, ZX=4096, K=1024, M=256, N=4096 ----
    sample_max_kernel<<<dim3(256, BVAL), 256>>>(x3, c2, v2, 256, 64, 4096);
    gemm_bias_silu_kernel<<<dim3(4096 / BN, 256 / BM, BVAL), 256>>>(
        w2, v2, b2, out + off_bev2, 256, 4096, 1024);

    // ---- scale 4: C=512, H=W=32, ZX=1024, K=2048, M=512, N=1024 ----
    sample_max_kernel<<<dim3(512, BVAL), 256>>>(x4, c4, v4, 512, 32, 1024);
    gemm_bias_silu_kernel<<<dim3(1024 / BN, 512 / BM, BVAL), 256>>>(
        w4, v4, b4, out + off_bev4, 512, 1024, 2048);

    // ---- scale 8: C=1024, H=W=16, ZX=256, K=4096, M=1024, N=256 ----
    sample_max_kernel<<<dim3(1024, BVAL), 256>>>(x5, c8, v8, 1024, 16, 256);
    gemm_bias_silu_kernel<<<dim3(256 / BN, 1024 / BM, BVAL), 256>>>(
        w8, v8, b8, out + off_bev8, 1024, 256, 4096);

    // ---- valid voxel mask (scale-2 coords only), N = 4*64*64 = 16384 ----
    mask_kernel<<<(BVAL * 16384 + 255) / 256, 256>>>(c2, out + off_mask, 16384);
}

// round 4
// speedup vs baseline: 1.0079x; 1.0078x over previous
#include <cuda_runtime.h>
#include <cuda_bf16.h>
#include <math.h>

// ---------------------------------------------------------------------------
// IPMTrans: 3-scale BEV transform
//   per scale: v[b, c*Y+y, zx] = max_{s<4}( valid ? bilinear(feat[b*4+s,c], coord) : 0 )
//              bev[b,o,zx]    = silu( sum_i w[o,i]*v[b,i,zx] + bias[o] )
//   mask[b,n] = max_s valid(scale2 coords)
// Output concat: bev2 (2,256,4096) | bev4 (2,512,1024) | bev8 (2,1024,256) | mask (2,16384)
// ---------------------------------------------------------------------------

#define BVAL 2
#define SVAL 4
#define YVAL 4

// scratch for the max-pooled sampled features (GEMM inputs)
__device__ float g_v2[2ULL * 1024 * 4096];   // (B, 256*Y, 64*64)
__device__ float g_v4[2ULL * 2048 * 1024];   // (B, 512*Y, 32*32)
__device__ float g_v8[2ULL * 4096 * 256];    // (B, 1024*Y, 16*16)

// ---------------------------------------------------------------------------
// Kernel 1: bilinear sample + mask + max over S.
// grid = (C, B). Each block owns one (b, c) pair; loops over Y*ZX outputs.
// Working set: 4 channel planes (one per s) = 4*H*W*4 bytes <= 64KB -> L1.
// ---------------------------------------------------------------------------
__global__ void sample_max_kernel(const float* __restrict__ feat,
                                  const float* __restrict__ coords,
                                  float* __restrict__ v,
                                  int C, int Wd, int ZX)
{
    const int c = blockIdx.x;
    const int b = blockIdx.y;
    const int HW = Wd * Wd;
    const int N = YVAL * ZX;
    const float sc = 0.5f * (float)(Wd - 1);

    const float2* __restrict__ crd = (const float2*)coords;

    // per-(b,c) plane base pointers for the 4 sweeps
    const float* __restrict__ p0 = feat + ((size_t)(b * SVAL + 0) * C + c) * HW;
    const float* __restrict__ p1 = feat + ((size_t)(b * SVAL + 1) * C + c) * HW;
    const float* __restrict__ p2 = feat + ((size_t)(b * SVAL + 2) * C + c) * HW;
    const float* __restrict__ p3 = feat + ((size_t)(b * SVAL + 3) * C + c) * HW;
    const float* planes[SVAL] = {p0, p1, p2, p3};

    float* __restrict__ vout = v + ((size_t)(b * C + c) * YVAL) * (size_t)ZX;

    for (int idx = threadIdx.x; idx < N; idx += blockDim.x) {
        float vmax = -INFINITY;
#pragma unroll
        for (int s = 0; s < SVAL; s++) {
            const int bs = b * SVAL + s;
            float2 g = crd[(size_t)bs * N + idx];

            float ix = (g.x + 1.0f) * sc;
            float iy = (g.y + 1.0f) * sc;
            float x0f = floorf(ix);
            float y0f = floorf(iy);
            float wx = ix - x0f;
            float wy = iy - y0f;
            int x0 = (int)x0f;
            int y0 = (int)y0f;
            x0 = min(max(x0, 0), Wd - 1);
            y0 = min(max(y0, 0), Wd - 1);
            int x1 = min(x0 + 1, Wd - 1);
            int y1 = min(y0 + 1, Wd - 1);

            const float* pl = planes[s];
            float v00 = pl[y0 * Wd + x0];
            float v01 = pl[y0 * Wd + x1];
            float v10 = pl[y1 * Wd + x0];
            float v11 = pl[y1 * Wd + x1];

            float samp = v00 * (1.0f - wx) * (1.0f - wy)
                       + v01 * wx * (1.0f - wy)
                       + v10 * (1.0f - wx) * wy
                       + v11 * wx * wy;

            bool valid = (g.x >= -1.0f) & (g.x <= 1.0f) & (g.y >= -1.0f) & (g.y <= 1.0f);
            float val = valid ? samp : 0.0f;
            vmax = fmaxf(vmax, val);
        }
        vout[idx] = vmax;
    }
}

// ---------------------------------------------------------------------------
// Kernel 2: batched fp32 GEMM + bias + silu.
//   out[z, m, n] = silu( bias[m] + sum_k W[m,k] * V[z,k,n] )
// BM=BN=64, BK=16, 256 threads, 4x4 per-thread microtile.
// ---------------------------------------------------------------------------
#define BM 64
#define BN 64
#define BK 16

__global__ __launch_bounds__(256) void gemm_bias_silu_kernel(
    const float* __restrict__ Wm, const float* __restrict__ V,
    const float* __restrict__ bias, float* __restrict__ out,
    int M, int N, int K)
{
    __shared__ float As[BK][BM];      // W tile, transposed: As[k][m]
    __shared__ float Bs[BK][BN];      // V tile: Bs[k][n]

    const int bn = blockIdx.x * BN;
    const int bm = blockIdx.y * BM;
    const int z  = blockIdx.z;

    const float* __restrict__ Vb = V + (size_t)z * K * N;
    float* __restrict__ outb = out + (size_t)z * M * N;

    const int tid = threadIdx.x;
    const int tx = tid & 15;          // 0..15 -> n
    const int ty = tid >> 4;          // 0..15 -> m

    float acc[4][4];
#pragma unroll
    for (int i = 0; i < 4; i++)
#pragma unroll
        for (int j = 0; j < 4; j++) acc[i][j] = 0.0f;

    for (int k0 = 0; k0 < K; k0 += BK) {
        // load W tile (BM x BK): each thread one float4 along k
        {
            int r = tid >> 2;                 // 0..63 (m)
            int cc = (tid & 3) * 4;           // 0,4,8,12 (k)
            float4 t = *(const float4*)&Wm[(size_t)(bm + r) * K + k0 + cc];
            As[cc + 0][r] = t.x;
            As[cc + 1][r] = t.y;
            As[cc + 2][r] = t.z;
            As[cc + 3][r] = t.w;
        }
        // load V tile (BK x BN): 1024 elems, 4 per thread, coalesced on n
#pragma unroll
        for (int j = 0; j < 4; j++) {
            int e = tid + j * 256;
            int r = e >> 6;                   // k
            int cc = e & 63;                  // n
            Bs[r][cc] = Vb[(size_t)(k0 + r) * N + bn + cc];
        }
        __syncthreads();

#pragma unroll
        for (int kk = 0; kk < BK; kk++) {
            float4 a4 = *(const float4*)&As[kk][ty * 4];
            float4 b4 = *(const float4*)&Bs[kk][tx * 4];
            float av[4] = {a4.x, a4.y, a4.z, a4.w};
            float bv[4] = {b4.x, b4.y, b4.z, b4.w};
#pragma unroll
            for (int i = 0; i < 4; i++)
#pragma unroll
                for (int j = 0; j < 4; j++)
                    acc[i][j] = fmaf(av[i], bv[j], acc[i][j]);
        }
        __syncthreads();
    }

    // epilogue: bias + silu
#pragma unroll
    for (int i = 0; i < 4; i++) {
        int m = bm + ty * 4 + i;
        float bs = bias[m];
#pragma unroll
        for (int j = 0; j < 4; j++) {
            int n = bn + tx * 4 + j;
            float x = acc[i][j] + bs;
            float s = x / (1.0f + expf(-x));
            outb[(size_t)m * N + n] = s;
        }
    }
}

// ---------------------------------------------------------------------------
// Kernel 3: valid voxel mask from scale-2 coords. out[b,n] = any_s valid
// ---------------------------------------------------------------------------
__global__ void mask_kernel(const float* __restrict__ coords,
                            float* __restrict__ out, int N)
{
    int i = blockIdx.x * blockDim.x + threadIdx.x;
    if (i >= BVAL * N) return;
    int b = i / N;
    int n = i % N;
    const float2* __restrict__ crd = (const float2*)coords;
    float m = 0.0f;
#pragma unroll
    for (int s = 0; s < SVAL; s++) {
        float2 g = crd[(size_t)(b * SVAL + s) * N + n];
        bool valid = (g.x >= -1.0f) & (g.x <= 1.0f) & (g.y >= -1.0f) & (g.y <= 1.0f);
        if (valid) m = 1.0f;
    }
    out[i] = m;
}

// ---------------------------------------------------------------------------
// launch
// ---------------------------------------------------------------------------
extern "C" void kernel_launch(void* const* d_in, const int* in_sizes, int n_in,
                              void* d_out, int out_size)
{
    const float* x3 = (const float*)d_in[0];
    const float* x4 = (const float*)d_in[1];
    const float* x5 = (const float*)d_in[2];
    const float* c2 = (const float*)d_in[3];
    const float* c4 = (const float*)d_in[4];
    const float* c8 = (const float*)d_in[5];
    const float* w2 = (const float*)d_in[6];
    const float* b2 = (const float*)d_in[7];
    const float* w4 = (const float*)d_in[8];
    const float* b4 = (const float*)d_in[9];
    const float* w8 = (const float*)d_in[10];
    const float* b8 = (const float*)d_in[11];

    float* out = (float*)d_out;

    float *v2, *v4, *v8;
    cudaGetSymbolAddress((void**)&v2, g_v2);
    cudaGetSymbolAddress((void**)&v4, g_v4);
    cudaGetSymbolAddress((void**)&v8, g_v8);

    // output layout offsets
    const size_t off_bev2 = 0;
    const size_t off_bev4 = off_bev2 + 2ULL * 256 * 4096;   // 2,097,152
    const size_t off_bev8 = off_bev4 + 2ULL * 512 * 1024;   // 3,145,728
    const size_t off_mask = off_bev8 + 2ULL * 1024 * 256;   // 3,670,016

    // ---- scale 2: C=256, H=W=64, ZX=4096, K=1024, M=256, N=4096 ----
    sample_max_kernel<<<dim3(256, BVAL), 256>>>(x3, c2, v2, 256, 64, 4096);
    gemm_bias_silu_kernel<<<dim3(4096 / BN, 256 / BM, BVAL), 256>>>(
        w2, v2, b2, out + off_bev2, 256, 4096, 1024);

    // ---- scale 4: C=512, H=W=32, ZX=1024, K=2048, M=512, N=1024 ----
    sample_max_kernel<<<dim3(512, BVAL), 256>>>(x4, c4, v4, 512, 32, 1024);
    gemm_bias_silu_kernel<<<dim3(1024 / BN, 512 / BM, BVAL), 256>>>(
        w4, v4, b4, out + off_bev4, 512, 1024, 2048);

    // ---- scale 8: C=1024, H=W=16, ZX=256, K=4096, M=1024, N=256 ----
    sample_max_kernel<<<dim3(1024, BVAL), 256>>>(x5, c8, v8, 1024, 16, 256);
    gemm_bias_silu_kernel<<<dim3(256 / BN, 1024 / BM, BVAL), 256>>>(
        w8, v8, b8, out + off_bev8, 1024, 256, 4096);

    // ---- valid voxel mask (scale-2 coords only), N = 4*64*64 = 16384 ----
    mask_kernel<<<(BVAL * 16384 + 255) / 256, 256>>>(c2, out + off_mask, 16384);
}

// round 6
// speedup vs baseline: 2.4672x; 2.4479x over previous
#include <cuda_runtime.h>
#include <cuda_bf16.h>
#include <cstdint>
#include <math.h>

// ---------------------------------------------------------------------------
// IPMTrans: 3-scale BEV transform, mma.sync (HMMA bf16) edition.
//   sample+max -> v_hi / v_lo bf16 scratch, [K][N] n-contiguous
//   W fp32     -> Whi/Wlo bf16 scratch,     [M][K] k-contiguous
//   GEMM       -> mma.sync m16n8k16 bf16, 3-pass split (hihi + hilo + lohi),
//                 cp.async double-buffered smem, ldmatrix(+trans)
//   epilogue   -> bias + silu, fp32 out
// Output: bev2 (2,256,4096) | bev4 (2,512,1024) | bev8 (2,1024,256) | mask (2,16384)
// ---------------------------------------------------------------------------

#define BVAL 2
#define SVAL 4
#define YVAL 4

// ------------------------- scratch (device globals) ------------------------
__device__ __align__(16) __nv_bfloat16 g_v2hi[2u * 1024u * 4096u];
__device__ __align__(16) __nv_bfloat16 g_v2lo[2u * 1024u * 4096u];
__device__ __align__(16) __nv_bfloat16 g_v4hi[2u * 2048u * 1024u];
__device__ __align__(16) __nv_bfloat16 g_v4lo[2u * 2048u * 1024u];
__device__ __align__(16) __nv_bfloat16 g_v8hi[2u * 4096u * 256u];
__device__ __align__(16) __nv_bfloat16 g_v8lo[2u * 4096u * 256u];
__device__ __align__(16) __nv_bfloat16 g_w2hi[256u * 1024u];
__device__ __align__(16) __nv_bfloat16 g_w2lo[256u * 1024u];
__device__ __align__(16) __nv_bfloat16 g_w4hi[512u * 2048u];
__device__ __align__(16) __nv_bfloat16 g_w4lo[512u * 2048u];
__device__ __align__(16) __nv_bfloat16 g_w8hi[1024u * 4096u];
__device__ __align__(16) __nv_bfloat16 g_w8lo[1024u * 4096u];

// ------------------------- PTX helpers -------------------------------------
__device__ __forceinline__ uint32_t smem_u32(const void* p) {
    uint32_t a;
    asm("{ .reg .u64 t; cvta.to.shared.u64 t, %1; cvt.u32.u64 %0, t; }" : "=r"(a) : "l"(p));
    return a;
}
__device__ __forceinline__ void cp16(uint32_t dst, const void* src) {
    asm volatile("cp.async.cg.shared.global [%0], [%1], 16;" :: "r"(dst), "l"(src));
}
#define CP_COMMIT() asm volatile("cp.async.commit_group;" ::: "memory")
#define CP_WAIT1()  asm volatile("cp.async.wait_group 1;" ::: "memory")

__device__ __forceinline__ void ldsm4(uint32_t* r, uint32_t addr) {
    asm volatile("ldmatrix.sync.aligned.m8n8.x4.shared.b16 {%0,%1,%2,%3}, [%4];"
        : "=r"(r[0]), "=r"(r[1]), "=r"(r[2]), "=r"(r[3]) : "r"(addr));
}
__device__ __forceinline__ void ldsm4t(uint32_t* r, uint32_t addr) {
    asm volatile("ldmatrix.sync.aligned.m8n8.x4.trans.shared.b16 {%0,%1,%2,%3}, [%4];"
        : "=r"(r[0]), "=r"(r[1]), "=r"(r[2]), "=r"(r[3]) : "r"(addr));
}
__device__ __forceinline__ void mma16816(float* d, const uint32_t* a, const uint32_t* b) {
    asm volatile(
        "mma.sync.aligned.m16n8k16.row.col.f32.bf16.bf16.f32 "
        "{%0,%1,%2,%3}, {%4,%5,%6,%7}, {%8,%9}, {%0,%1,%2,%3};"
        : "+f"(d[0]), "+f"(d[1]), "+f"(d[2]), "+f"(d[3])
        : "r"(a[0]), "r"(a[1]), "r"(a[2]), "r"(a[3]), "r"(b[0]), "r"(b[1]));
}

// ---------------------------------------------------------------------------
// Kernel 0: split W fp32 -> bf16 hi/lo
// ---------------------------------------------------------------------------
__global__ void wsplit_kernel(const float* __restrict__ w,
                              __nv_bfloat16* __restrict__ hi,
                              __nv_bfloat16* __restrict__ lo, int n)
{
    int i = blockIdx.x * blockDim.x + threadIdx.x;
    if (i >= n) return;
    float a = w[i];
    __nv_bfloat16 h = __float2bfloat16(a);
    float r = a - __bfloat162float(h);
    hi[i] = h;
    lo[i] = __float2bfloat16(r);
}

// ---------------------------------------------------------------------------
// Kernel 1: bilinear sample + mask + max over S, planes staged in SMEM,
// output separate bf16 hi / lo planes.  grid = (C, B), 256 threads.
// ---------------------------------------------------------------------------
__global__ __launch_bounds__(256) void sample_split_kernel(
    const float* __restrict__ feat, const float* __restrict__ coords,
    __nv_bfloat16* __restrict__ vhi, __nv_bfloat16* __restrict__ vlo,
    int C, int Wd, int ZX)
{
    extern __shared__ float sp[];           // 4 * HW floats
    const int c = blockIdx.x;
    const int b = blockIdx.y;
    const int HW = Wd * Wd;
    const int N = YVAL * ZX;
    const float sc = 0.5f * (float)(Wd - 1);

    for (int s = 0; s < SVAL; s++) {
        const float4* src = (const float4*)(feat + ((size_t)(b * SVAL + s) * C + c) * (size_t)HW);
        float4* dst = (float4*)(sp + s * HW);
        for (int i = threadIdx.x; i < HW / 4; i += blockDim.x)
            dst[i] = src[i];
    }
    __syncthreads();

    const float2* __restrict__ crd = (const float2*)coords;
    size_t row = ((size_t)(b * C + c) * YVAL) * (size_t)ZX;
    __nv_bfloat16* __restrict__ oh = vhi + row;
    __nv_bfloat16* __restrict__ ol = vlo + row;

    for (int idx = threadIdx.x; idx < N; idx += blockDim.x) {
        float vmax = -INFINITY;
#pragma unroll
        for (int s = 0; s < SVAL; s++) {
            const int bs = b * SVAL + s;
            float2 g = crd[(size_t)bs * N + idx];

            float ix = (g.x + 1.0f) * sc;
            float iy = (g.y + 1.0f) * sc;
            float x0f = floorf(ix);
            float y0f = floorf(iy);
            float wx = ix - x0f;
            float wy = iy - y0f;
            int x0 = (int)x0f;
            int y0 = (int)y0f;
            x0 = min(max(x0, 0), Wd - 1);
            y0 = min(max(y0, 0), Wd - 1);
            int x1 = min(x0 + 1, Wd - 1);
            int y1 = min(y0 + 1, Wd - 1);

            const float* pl = sp + s * HW;
            float v00 = pl[y0 * Wd + x0];
            float v01 = pl[y0 * Wd + x1];
            float v10 = pl[y1 * Wd + x0];
            float v11 = pl[y1 * Wd + x1];

            float samp = v00 * (1.0f - wx) * (1.0f - wy)
                       + v01 * wx * (1.0f - wy)
                       + v10 * (1.0f - wx) * wy
                       + v11 * wx * wy;

            bool valid = (g.x >= -1.0f) & (g.x <= 1.0f) & (g.y >= -1.0f) & (g.y <= 1.0f);
            float val = valid ? samp : 0.0f;
            vmax = fmaxf(vmax, val);
        }
        __nv_bfloat16 h = __float2bfloat16(vmax);
        float r = vmax - __bfloat162float(h);
        oh[idx] = h;
        ol[idx] = __float2bfloat16(r);
    }
}

// ---------------------------------------------------------------------------
// Kernel 2: mma.sync bf16 GEMM + bias + silu.
//   out[z,m,n] = silu(bias[m] + sum_k W[m,k]*V[z,k,n])
// A = Whi/Wlo [M][K] k-contig; B = Vhi/Vlo [K][N] n-contig (ldmatrix.trans).
// BK=64, cp.async double buffer, warp grid 4x2, 3 MMA passes per k-step.
// ---------------------------------------------------------------------------
template <int BM, int BN>
__global__ __launch_bounds__(256) void gemm_mma_kernel(
    const __nv_bfloat16* __restrict__ Whi, const __nv_bfloat16* __restrict__ Wlo,
    const __nv_bfloat16* __restrict__ Vhi, const __nv_bfloat16* __restrict__ Vlo,
    const float* __restrict__ bias, float* __restrict__ out,
    int M, int N, int K)
{
    constexpr int WTM = BM / 4;          // warp tile m (32 or 16)
    constexpr int WTN = BN / 2;          // warp tile n (64 or 32)
    constexpr int MT = WTM / 16;         // m16 tiles per warp (2 or 1)
    constexpr int NT = WTN / 8;          // n8 tiles per warp (8 or 4)
    constexpr int A_PLANE = BM * 128;    // bytes: BM rows x 64 bf16
    constexpr int B_PLANE = 64 * BN * 2; // bytes: 64 k-rows x BN bf16
    constexpr int BRB = BN * 2;          // B row bytes
    constexpr int STAGE = 2 * A_PLANE + 2 * B_PLANE;

    extern __shared__ char smraw[];
    uint32_t sb = (smem_u32(smraw) + 1023u) & ~1023u;

    const int bn = blockIdx.x * BN;
    const int bm = blockIdx.y * BM;
    const int z  = blockIdx.z;
    const int tid = threadIdx.x;
    const int lane = tid & 31;
    const int wid = tid >> 5;
    const int wm = wid & 3;              // 0..3
    const int wn = wid >> 2;             // 0..1

    const __nv_bfloat16* __restrict__ Vhb = Vhi + (size_t)z * (size_t)K * (size_t)N;
    const __nv_bfloat16* __restrict__ Vlb = Vlo + (size_t)z * (size_t)K * (size_t)N;

    float acc[MT][NT][4];
#pragma unroll
    for (int i = 0; i < MT; i++)
#pragma unroll
        for (int j = 0; j < NT; j++)
#pragma unroll
            for (int q = 0; q < 4; q++) acc[i][j][q] = 0.0f;

    const int NC = K / 64;

    // ---- loader: stage a 64-k chunk into buffer s
    auto load_chunk = [&](int c, int s) {
        uint32_t st = sb + (uint32_t)s * STAGE;
        const int k0 = c * 64;
#pragma unroll 2
        for (int i = tid; i < BM * 8; i += 256) {
            int r = i >> 3, ch = i & 7;
            uint32_t off = (uint32_t)(r * 128 + ((ch ^ (r & 7)) << 4));
            size_t g = (size_t)(bm + r) * (size_t)K + (size_t)(k0 + ch * 8);
            cp16(st + off, Whi + g);
            cp16(st + A_PLANE + off, Wlo + g);
        }
#pragma unroll 2
        for (int i = tid; i < 64 * (BN / 8); i += 256) {
            int r = i / (BN / 8), ch = i % (BN / 8);
            uint32_t off = (uint32_t)(r * BRB + ((ch ^ (r & 7)) << 4));
            size_t g = (size_t)(k0 + r) * (size_t)N + (size_t)(bn + ch * 8);
            cp16(st + 2 * A_PLANE + off, Vhb + g);
            cp16(st + 2 * A_PLANE + B_PLANE + off, Vlb + g);
        }
    };

    load_chunk(0, 0);
    CP_COMMIT();

    for (int c = 0; c < NC; c++) {
        if (c + 1 < NC) load_chunk(c + 1, (c + 1) & 1);
        CP_COMMIT();                     // empty group on last iter keeps wait math uniform
        CP_WAIT1();
        __syncthreads();

        uint32_t st = sb + (uint32_t)(c & 1) * STAGE;
        uint32_t Ah = st, Al = st + A_PLANE;
        uint32_t Bh = st + 2 * A_PLANE, Bl = Bh + B_PLANE;

#pragma unroll
        for (int ks = 0; ks < 4; ks++) {
            // A fragments
            uint32_t ahi[MT][4], alo[MT][4];
#pragma unroll
            for (int mt = 0; mt < MT; mt++) {
                int r = wm * WTM + mt * 16 + (lane & 15);
                int ch = ks * 2 + (lane >> 4);
                uint32_t off = (uint32_t)(r * 128 + ((ch ^ (r & 7)) << 4));
                ldsm4(ahi[mt], Ah + off);
                ldsm4(alo[mt], Al + off);
            }
            // B fragments: x4.trans loads two n8 tiles at once
            uint32_t bhi[NT][2], blo[NT][2];
#pragma unroll
            for (int nt2 = 0; nt2 < NT / 2; nt2++) {
                int r = ks * 16 + (lane & 15);
                int ch = wn * NT + nt2 * 2 + (lane >> 4);
                uint32_t off = (uint32_t)(r * BRB + ((ch ^ (r & 7)) << 4));
                uint32_t t[4];
                ldsm4t(t, Bh + off);
                bhi[nt2 * 2][0] = t[0]; bhi[nt2 * 2][1] = t[1];
                bhi[nt2 * 2 + 1][0] = t[2]; bhi[nt2 * 2 + 1][1] = t[3];
                ldsm4t(t, Bl + off);
                blo[nt2 * 2][0] = t[0]; blo[nt2 * 2][1] = t[1];
                blo[nt2 * 2 + 1][0] = t[2]; blo[nt2 * 2 + 1][1] = t[3];
            }
            // 3-pass MMA
#pragma unroll
            for (int mt = 0; mt < MT; mt++)
#pragma unroll
                for (int nt = 0; nt < NT; nt++) {
                    mma16816(acc[mt][nt], ahi[mt], bhi[nt]);
                    mma16816(acc[mt][nt], ahi[mt], blo[nt]);
                    mma16816(acc[mt][nt], alo[mt], bhi[nt]);
                }
        }
        __syncthreads();
    }

    // ---- epilogue: bias + silu, direct fp32 stores
    float* ob = out + (size_t)z * (size_t)M * (size_t)N;
#pragma unroll
    for (int mt = 0; mt < MT; mt++) {
        int row0 = bm + wm * WTM + mt * 16 + (lane >> 2);
        float bs0 = bias[row0];
        float bs1 = bias[row0 + 8];
#pragma unroll
        for (int nt = 0; nt < NT; nt++) {
            int col = bn + wn * WTN + nt * 8 + (lane & 3) * 2;
            float x0 = acc[mt][nt][0] + bs0;
            float x1 = acc[mt][nt][1] + bs0;
            float x2 = acc[mt][nt][2] + bs1;
            float x3 = acc[mt][nt][3] + bs1;
            float2 r0 = make_float2(x0 / (1.0f + expf(-x0)), x1 / (1.0f + expf(-x1)));
            float2 r1 = make_float2(x2 / (1.0f + expf(-x2)), x3 / (1.0f + expf(-x3)));
            *(float2*)&ob[(size_t)row0 * N + col] = r0;
            *(float2*)&ob[(size_t)(row0 + 8) * N + col] = r1;
        }
    }
}

// ---------------------------------------------------------------------------
// Kernel 3: valid voxel mask from scale-2 coords. out[b,n] = any_s valid
// ---------------------------------------------------------------------------
__global__ void mask_kernel(const float* __restrict__ coords,
                            float* __restrict__ out, int N)
{
    int i = blockIdx.x * blockDim.x + threadIdx.x;
    if (i >= BVAL * N) return;
    int b = i / N;
    int n = i % N;
    const float2* __restrict__ crd = (const float2*)coords;
    float m = 0.0f;
#pragma unroll
    for (int s = 0; s < SVAL; s++) {
        float2 g = crd[(size_t)(b * SVAL + s) * N + n];
        bool valid = (g.x >= -1.0f) & (g.x <= 1.0f) & (g.y >= -1.0f) & (g.y <= 1.0f);
        if (valid) m = 1.0f;
    }
    out[i] = m;
}

// ---------------------------------------------------------------------------
// launch
// ---------------------------------------------------------------------------
extern "C" void kernel_launch(void* const* d_in, const int* in_sizes, int n_in,
                              void* d_out, int out_size)
{
    const float* x3 = (const float*)d_in[0];
    const float* x4 = (const float*)d_in[1];
    const float* x5 = (const float*)d_in[2];
    const float* c2 = (const float*)d_in[3];
    const float* c4 = (const float*)d_in[4];
    const float* c8 = (const float*)d_in[5];
    const float* w2 = (const float*)d_in[6];
    const float* b2 = (const float*)d_in[7];
    const float* w4 = (const float*)d_in[8];
    const float* b4 = (const float*)d_in[9];
    const float* w8 = (const float*)d_in[10];
    const float* b8 = (const float*)d_in[11];

    float* out = (float*)d_out;

    __nv_bfloat16 *v2h, *v2l, *v4h, *v4l, *v8h, *v8l;
    __nv_bfloat16 *w2h, *w2l, *w4h, *w4l, *w8h, *w8l;
    cudaGetSymbolAddress((void**)&v2h, g_v2hi);
    cudaGetSymbolAddress((void**)&v2l, g_v2lo);
    cudaGetSymbolAddress((void**)&v4h, g_v4hi);
    cudaGetSymbolAddress((void**)&v4l, g_v4lo);
    cudaGetSymbolAddress((void**)&v8h, g_v8hi);
    cudaGetSymbolAddress((void**)&v8l, g_v8lo);
    cudaGetSymbolAddress((void**)&w2h, g_w2hi);
    cudaGetSymbolAddress((void**)&w2l, g_w2lo);
    cudaGetSymbolAddress((void**)&w4h, g_w4hi);
    cudaGetSymbolAddress((void**)&w4l, g_w4lo);
    cudaGetSymbolAddress((void**)&w8h, g_w8hi);
    cudaGetSymbolAddress((void**)&w8l, g_w8lo);

    // dynamic smem sizes (stage = 2*A + 2*B planes, double buffered, +1KB align)
    const int sm2 = 2 * (2 * 128 * 128 + 2 * 64 * 128 * 2) + 1024;   // <128,128> = 132096
    const int sm4 = 2 * (2 * 64 * 128 + 2 * 64 * 128 * 2) + 1024;    // <64,128>  =  99328
    const int sm8 = 2 * (2 * 64 * 128 + 2 * 64 * 64 * 2) + 1024;     // <64,64>   =  66560

    cudaFuncSetAttribute(sample_split_kernel,
                         cudaFuncAttributeMaxDynamicSharedMemorySize, 65536);
    cudaFuncSetAttribute(gemm_mma_kernel<128, 128>,
                         cudaFuncAttributeMaxDynamicSharedMemorySize, sm2);
    cudaFuncSetAttribute(gemm_mma_kernel<64, 128>,
                         cudaFuncAttributeMaxDynamicSharedMemorySize, sm4);
    cudaFuncSetAttribute(gemm_mma_kernel<64, 64>,
                         cudaFuncAttributeMaxDynamicSharedMemorySize, sm8);

    const size_t off_bev2 = 0;
    const size_t off_bev4 = off_bev2 + 2ULL * 256 * 4096;
    const size_t off_bev8 = off_bev4 + 2ULL * 512 * 1024;
    const size_t off_mask = off_bev8 + 2ULL * 1024 * 256;

    // weight splits
    wsplit_kernel<<<(256 * 1024 + 255) / 256, 256>>>(w2, w2h, w2l, 256 * 1024);
    wsplit_kernel<<<(512 * 2048 + 255) / 256, 256>>>(w4, w4h, w4l, 512 * 2048);
    wsplit_kernel<<<(1024 * 4096 + 255) / 256, 256>>>(w8, w8h, w8l, 1024 * 4096);

    // samplers (planes staged in smem)
    sample_split_kernel<<<dim3(256, BVAL), 256, 4 * 64 * 64 * 4>>>(x3, c2, v2h, v2l, 256, 64, 4096);
    sample_split_kernel<<<dim3(512, BVAL), 256, 4 * 32 * 32 * 4>>>(x4, c4, v4h, v4l, 512, 32, 1024);
    sample_split_kernel<<<dim3(1024, BVAL), 256, 4 * 16 * 16 * 4>>>(x5, c8, v8h, v8l, 1024, 16, 256);

    // GEMMs: each exactly 128 blocks (one full wave)
    gemm_mma_kernel<128, 128><<<dim3(4096 / 128, 256 / 128, BVAL), 256, sm2>>>(
        w2h, w2l, v2h, v2l, b2, out + off_bev2, 256, 4096, 1024);
    gemm_mma_kernel<64, 128><<<dim3(1024 / 128, 512 / 64, BVAL), 256, sm4>>>(
        w4h, w4l, v4h, v4l, b4, out + off_bev4, 512, 1024, 2048);
    gemm_mma_kernel<64, 64><<<dim3(256 / 64, 1024 / 64, BVAL), 256, sm8>>>(
        w8h, w8l, v8h, v8l, b8, out + off_bev8, 1024, 256, 4096);

    // valid voxel mask
    mask_kernel<<<(BVAL * 16384 + 255) / 256, 256>>>(c2, out + off_mask, 16384);
}

// round 7
// speedup vs baseline: 3.0685x; 1.2437x over previous
#include <cuda_runtime.h>
#include <cuda_bf16.h>
#include <cstdint>
#include <math.h>

// ---------------------------------------------------------------------------
// IPMTrans: 3-scale BEV transform, mma.sync (HMMA bf16) edition, round 7.
//   precomp    -> per-(bs,idx) packed gather addr + fp32 weights (shared by all C)
//   sample+max -> v_hi / v_lo bf16 scratch, [K][N] n-contiguous (planes in smem)
//   W fp32     -> Whi/Wlo bf16 scratch,     [M][K] k-contiguous
//   GEMM       -> mma.sync m16n8k16 bf16, 3-pass split, cp.async double buffer
//   3 streams  -> per-scale chains overlap (sampler=LDS/issue vs GEMM=tensor)
// Output: bev2 (2,256,4096) | bev4 (2,512,1024) | bev8 (2,1024,256) | mask (2,16384)
// ---------------------------------------------------------------------------

#define BVAL 2
#define SVAL 4
#define YVAL 4

// ------------------------- scratch (device globals) ------------------------
__device__ __align__(16) __nv_bfloat16 g_v2hi[2u * 1024u * 4096u];
__device__ __align__(16) __nv_bfloat16 g_v2lo[2u * 1024u * 4096u];
__device__ __align__(16) __nv_bfloat16 g_v4hi[2u * 2048u * 1024u];
__device__ __align__(16) __nv_bfloat16 g_v4lo[2u * 2048u * 1024u];
__device__ __align__(16) __nv_bfloat16 g_v8hi[2u * 4096u * 256u];
__device__ __align__(16) __nv_bfloat16 g_v8lo[2u * 4096u * 256u];
__device__ __align__(16) __nv_bfloat16 g_w2hi[256u * 1024u];
__device__ __align__(16) __nv_bfloat16 g_w2lo[256u * 1024u];
__device__ __align__(16) __nv_bfloat16 g_w4hi[512u * 2048u];
__device__ __align__(16) __nv_bfloat16 g_w4lo[512u * 2048u];
__device__ __align__(16) __nv_bfloat16 g_w8hi[1024u * 4096u];
__device__ __align__(16) __nv_bfloat16 g_w8lo[1024u * 4096u];
__device__ __align__(16) uint4 g_pre2[8u * 16384u];
__device__ __align__(16) uint4 g_pre4[8u * 4096u];
__device__ __align__(16) uint4 g_pre8[8u * 1024u];

// ------------------------- PTX helpers -------------------------------------
__device__ __forceinline__ uint32_t smem_u32(const void* p) {
    uint32_t a;
    asm("{ .reg .u64 t; cvta.to.shared.u64 t, %1; cvt.u32.u64 %0, t; }" : "=r"(a) : "l"(p));
    return a;
}
__device__ __forceinline__ void cp16(uint32_t dst, const void* src) {
    asm volatile("cp.async.cg.shared.global [%0], [%1], 16;" :: "r"(dst), "l"(src));
}
#define CP_COMMIT() asm volatile("cp.async.commit_group;" ::: "memory")
#define CP_WAIT1()  asm volatile("cp.async.wait_group 1;" ::: "memory")

__device__ __forceinline__ void ldsm4(uint32_t* r, uint32_t addr) {
    asm volatile("ldmatrix.sync.aligned.m8n8.x4.shared.b16 {%0,%1,%2,%3}, [%4];"
        : "=r"(r[0]), "=r"(r[1]), "=r"(r[2]), "=r"(r[3]) : "r"(addr));
}
__device__ __forceinline__ void ldsm4t(uint32_t* r, uint32_t addr) {
    asm volatile("ldmatrix.sync.aligned.m8n8.x4.trans.shared.b16 {%0,%1,%2,%3}, [%4];"
        : "=r"(r[0]), "=r"(r[1]), "=r"(r[2]), "=r"(r[3]) : "r"(addr));
}
__device__ __forceinline__ void mma16816(float* d, const uint32_t* a, const uint32_t* b) {
    asm volatile(
        "mma.sync.aligned.m16n8k16.row.col.f32.bf16.bf16.f32 "
        "{%0,%1,%2,%3}, {%4,%5,%6,%7}, {%8,%9}, {%0,%1,%2,%3};"
        : "+f"(d[0]), "+f"(d[1]), "+f"(d[2]), "+f"(d[3])
        : "r"(a[0]), "r"(a[1]), "r"(a[2]), "r"(a[3]), "r"(b[0]), "r"(b[1]));
}

// ---------------------------------------------------------------------------
// Kernel P: precompute gather descriptors, shared by every channel block.
//   pre.x = a0 | dx<<15 | a1<<16   (a0/a1 = clipped row addrs; sentinel HW when
//   invalid, with wx=wy=0 -> sample = plane[HW] = 0)
//   pre.y = wx (fp32 bits), pre.z = wy, pre.w unused
// ---------------------------------------------------------------------------
__global__ void precomp_kernel(const float* __restrict__ coords,
                               uint4* __restrict__ pre,
                               int Wd, int total)
{
    int i = blockIdx.x * blockDim.x + threadIdx.x;
    if (i >= total) return;
    float2 g = ((const float2*)coords)[i];
    const int HW = Wd * Wd;
    const float sc = 0.5f * (float)(Wd - 1);

    float ix = (g.x + 1.0f) * sc;
    float iy = (g.y + 1.0f) * sc;
    float x0f = floorf(ix);
    float y0f = floorf(iy);
    float wx = ix - x0f;
    float wy = iy - y0f;
    int x0 = min(max((int)x0f, 0), Wd - 1);
    int y0 = min(max((int)y0f, 0), Wd - 1);
    int x1 = min(x0 + 1, Wd - 1);
    int y1 = min(y0 + 1, Wd - 1);
    bool valid = (g.x >= -1.0f) & (g.x <= 1.0f) & (g.y >= -1.0f) & (g.y <= 1.0f);

    int a0 = y0 * Wd + x0;
    int a1 = y1 * Wd + x0;
    int dx = x1 - x0;
    if (!valid) { a0 = HW; a1 = HW; dx = 0; wx = 0.0f; wy = 0.0f; }

    pre[i] = make_uint4((uint32_t)a0 | ((uint32_t)dx << 15) | ((uint32_t)a1 << 16),
                        __float_as_uint(wx), __float_as_uint(wy), 0u);
}

// ---------------------------------------------------------------------------
// Kernel 0: split W fp32 -> bf16 hi/lo
// ---------------------------------------------------------------------------
__global__ void wsplit_kernel(const float* __restrict__ w,
                              __nv_bfloat16* __restrict__ hi,
                              __nv_bfloat16* __restrict__ lo, int n)
{
    int i = blockIdx.x * blockDim.x + threadIdx.x;
    if (i >= n) return;
    float a = w[i];
    __nv_bfloat16 h = __float2bfloat16(a);
    float r = a - __bfloat162float(h);
    hi[i] = h;
    lo[i] = __float2bfloat16(r);
}

// ---------------------------------------------------------------------------
// Kernel 1: gather + max over S using precomputed descriptors.
// grid = (C, B), 256 threads. Planes (+ zero sentinel) staged in smem.
// ---------------------------------------------------------------------------
__global__ __launch_bounds__(256) void sample_split_kernel(
    const float* __restrict__ feat, const uint4* __restrict__ pre,
    __nv_bfloat16* __restrict__ vhi, __nv_bfloat16* __restrict__ vlo,
    int C, int Wd, int ZX)
{
    extern __shared__ float sp[];           // 4 * (HW+4) floats
    const int c = blockIdx.x;
    const int b = blockIdx.y;
    const int HW = Wd * Wd;
    const int HWP = HW + 4;
    const int N = YVAL * ZX;

    for (int s = 0; s < SVAL; s++) {
        const float4* src = (const float4*)(feat + ((size_t)(b * SVAL + s) * C + c) * (size_t)HW);
        float4* dst = (float4*)(sp + s * HWP);
        for (int i = threadIdx.x; i < HW / 4; i += blockDim.x)
            dst[i] = src[i];
    }
    if (threadIdx.x < SVAL) sp[threadIdx.x * HWP + HW] = 0.0f;   // sentinel
    __syncthreads();

    size_t row = ((size_t)(b * C + c) * YVAL) * (size_t)ZX;
    __nv_bfloat16* __restrict__ oh = vhi + row;
    __nv_bfloat16* __restrict__ ol = vlo + row;

    for (int idx = threadIdx.x; idx < N; idx += blockDim.x) {
        float vmax = -INFINITY;
#pragma unroll
        for (int s = 0; s < SVAL; s++) {
            uint4 u = pre[(size_t)(b * SVAL + s) * N + idx];
            int a0 = u.x & 0x7FFF;
            int dx = (u.x >> 15) & 1;
            int a1 = u.x >> 16;
            float wx = __uint_as_float(u.y);
            float wy = __uint_as_float(u.z);
            const float* pl = sp + s * HWP;
            float v00 = pl[a0];
            float v01 = pl[a0 + dx];
            float v10 = pl[a1];
            float v11 = pl[a1 + dx];
            float v0 = fmaf(wx, v01 - v00, v00);
            float v1 = fmaf(wx, v11 - v10, v10);
            float sm = fmaf(wy, v1 - v0, v0);
            vmax = fmaxf(vmax, sm);
        }
        __nv_bfloat16 h = __float2bfloat16(vmax);
        float r = vmax - __bfloat162float(h);
        oh[idx] = h;
        ol[idx] = __float2bfloat16(r);
    }
}

// ---------------------------------------------------------------------------
// Kernel 2: mma.sync bf16 GEMM + bias + silu (unchanged from R6).
// ---------------------------------------------------------------------------
template <int BM, int BN>
__global__ __launch_bounds__(256) void gemm_mma_kernel(
    const __nv_bfloat16* __restrict__ Whi, const __nv_bfloat16* __restrict__ Wlo,
    const __nv_bfloat16* __restrict__ Vhi, const __nv_bfloat16* __restrict__ Vlo,
    const float* __restrict__ bias, float* __restrict__ out,
    int M, int N, int K)
{
    constexpr int WTM = BM / 4;
    constexpr int WTN = BN / 2;
    constexpr int MT = WTM / 16;
    constexpr int NT = WTN / 8;
    constexpr int A_PLANE = BM * 128;
    constexpr int B_PLANE = 64 * BN * 2;
    constexpr int BRB = BN * 2;
    constexpr int STAGE = 2 * A_PLANE + 2 * B_PLANE;

    extern __shared__ char smraw[];
    uint32_t sb = (smem_u32(smraw) + 1023u) & ~1023u;

    const int bn = blockIdx.x * BN;
    const int bm = blockIdx.y * BM;
    const int z  = blockIdx.z;
    const int tid = threadIdx.x;
    const int lane = tid & 31;
    const int wid = tid >> 5;
    const int wm = wid & 3;
    const int wn = wid >> 2;

    const __nv_bfloat16* __restrict__ Vhb = Vhi + (size_t)z * (size_t)K * (size_t)N;
    const __nv_bfloat16* __restrict__ Vlb = Vlo + (size_t)z * (size_t)K * (size_t)N;

    float acc[MT][NT][4];
#pragma unroll
    for (int i = 0; i < MT; i++)
#pragma unroll
        for (int j = 0; j < NT; j++)
#pragma unroll
            for (int q = 0; q < 4; q++) acc[i][j][q] = 0.0f;

    const int NC = K / 64;

    auto load_chunk = [&](int c, int s) {
        uint32_t st = sb + (uint32_t)s * STAGE;
        const int k0 = c * 64;
#pragma unroll 2
        for (int i = tid; i < BM * 8; i += 256) {
            int r = i >> 3, ch = i & 7;
            uint32_t off = (uint32_t)(r * 128 + ((ch ^ (r & 7)) << 4));
            size_t g = (size_t)(bm + r) * (size_t)K + (size_t)(k0 + ch * 8);
            cp16(st + off, Whi + g);
            cp16(st + A_PLANE + off, Wlo + g);
        }
#pragma unroll 2
        for (int i = tid; i < 64 * (BN / 8); i += 256) {
            int r = i / (BN / 8), ch = i % (BN / 8);
            uint32_t off = (uint32_t)(r * BRB + ((ch ^ (r & 7)) << 4));
            size_t g = (size_t)(k0 + r) * (size_t)N + (size_t)(bn + ch * 8);
            cp16(st + 2 * A_PLANE + off, Vhb + g);
            cp16(st + 2 * A_PLANE + B_PLANE + off, Vlb + g);
        }
    };

    load_chunk(0, 0);
    CP_COMMIT();

    for (int c = 0; c < NC; c++) {
        if (c + 1 < NC) load_chunk(c + 1, (c + 1) & 1);
        CP_COMMIT();
        CP_WAIT1();
        __syncthreads();

        uint32_t st = sb + (uint32_t)(c & 1) * STAGE;
        uint32_t Ah = st, Al = st + A_PLANE;
        uint32_t Bh = st + 2 * A_PLANE, Bl = Bh + B_PLANE;

#pragma unroll
        for (int ks = 0; ks < 4; ks++) {
            uint32_t ahi[MT][4], alo[MT][4];
#pragma unroll
            for (int mt = 0; mt < MT; mt++) {
                int r = wm * WTM + mt * 16 + (lane & 15);
                int ch = ks * 2 + (lane >> 4);
                uint32_t off = (uint32_t)(r * 128 + ((ch ^ (r & 7)) << 4));
                ldsm4(ahi[mt], Ah + off);
                ldsm4(alo[mt], Al + off);
            }
            uint32_t bhi[NT][2], blo[NT][2];
#pragma unroll
            for (int nt2 = 0; nt2 < NT / 2; nt2++) {
                int r = ks * 16 + (lane & 15);
                int ch = wn * NT + nt2 * 2 + (lane >> 4);
                uint32_t off = (uint32_t)(r * BRB + ((ch ^ (r & 7)) << 4));
                uint32_t t[4];
                ldsm4t(t, Bh + off);
                bhi[nt2 * 2][0] = t[0]; bhi[nt2 * 2][1] = t[1];
                bhi[nt2 * 2 + 1][0] = t[2]; bhi[nt2 * 2 + 1][1] = t[3];
                ldsm4t(t, Bl + off);
                blo[nt2 * 2][0] = t[0]; blo[nt2 * 2][1] = t[1];
                blo[nt2 * 2 + 1][0] = t[2]; blo[nt2 * 2 + 1][1] = t[3];
            }
#pragma unroll
            for (int mt = 0; mt < MT; mt++)
#pragma unroll
                for (int nt = 0; nt < NT; nt++) {
                    mma16816(acc[mt][nt], ahi[mt], bhi[nt]);
                    mma16816(acc[mt][nt], ahi[mt], blo[nt]);
                    mma16816(acc[mt][nt], alo[mt], bhi[nt]);
                }
        }
        __syncthreads();
    }

    float* ob = out + (size_t)z * (size_t)M * (size_t)N;
#pragma unroll
    for (int mt = 0; mt < MT; mt++) {
        int row0 = bm + wm * WTM + mt * 16 + (lane >> 2);
        float bs0 = bias[row0];
        float bs1 = bias[row0 + 8];
#pragma unroll
        for (int nt = 0; nt < NT; nt++) {
            int col = bn + wn * WTN + nt * 8 + (lane & 3) * 2;
            float x0 = acc[mt][nt][0] + bs0;
            float x1 = acc[mt][nt][1] + bs0;
            float x2 = acc[mt][nt][2] + bs1;
            float x3 = acc[mt][nt][3] + bs1;
            float2 r0 = make_float2(x0 / (1.0f + expf(-x0)), x1 / (1.0f + expf(-x1)));
            float2 r1 = make_float2(x2 / (1.0f + expf(-x2)), x3 / (1.0f + expf(-x3)));
            *(float2*)&ob[(size_t)row0 * N + col] = r0;
            *(float2*)&ob[(size_t)(row0 + 8) * N + col] = r1;
        }
    }
}

// ---------------------------------------------------------------------------
// Kernel 3: valid voxel mask from scale-2 coords.
// ---------------------------------------------------------------------------
__global__ void mask_kernel(const float* __restrict__ coords,
                            float* __restrict__ out, int N)
{
    int i = blockIdx.x * blockDim.x + threadIdx.x;
    if (i >= BVAL * N) return;
    int b = i / N;
    int n = i % N;
    const float2* __restrict__ crd = (const float2*)coords;
    float m = 0.0f;
#pragma unroll
    for (int s = 0; s < SVAL; s++) {
        float2 g = crd[(size_t)(b * SVAL + s) * N + n];
        bool valid = (g.x >= -1.0f) & (g.x <= 1.0f) & (g.y >= -1.0f) & (g.y <= 1.0f);
        if (valid) m = 1.0f;
    }
    out[i] = m;
}

// ---------------------------------------------------------------------------
// launch: 3 per-scale chains on side streams, forked/joined via events so the
// whole thing stays graph-capturable and the chains overlap.
// ---------------------------------------------------------------------------
extern "C" void kernel_launch(void* const* d_in, const int* in_sizes, int n_in,
                              void* d_out, int out_size)
{
    const float* x3 = (const float*)d_in[0];
    const float* x4 = (const float*)d_in[1];
    const float* x5 = (const float*)d_in[2];
    const float* c2 = (const float*)d_in[3];
    const float* c4 = (const float*)d_in[4];
    const float* c8 = (const float*)d_in[5];
    const float* w2 = (const float*)d_in[6];
    const float* b2 = (const float*)d_in[7];
    const float* w4 = (const float*)d_in[8];
    const float* b4 = (const float*)d_in[9];
    const float* w8 = (const float*)d_in[10];
    const float* b8 = (const float*)d_in[11];

    float* out = (float*)d_out;

    __nv_bfloat16 *v2h, *v2l, *v4h, *v4l, *v8h, *v8l;
    __nv_bfloat16 *w2h, *w2l, *w4h, *w4l, *w8h, *w8l;
    uint4 *p2, *p4, *p8;
    cudaGetSymbolAddress((void**)&v2h, g_v2hi);
    cudaGetSymbolAddress((void**)&v2l, g_v2lo);
    cudaGetSymbolAddress((void**)&v4h, g_v4hi);
    cudaGetSymbolAddress((void**)&v4l, g_v4lo);
    cudaGetSymbolAddress((void**)&v8h, g_v8hi);
    cudaGetSymbolAddress((void**)&v8l, g_v8lo);
    cudaGetSymbolAddress((void**)&w2h, g_w2hi);
    cudaGetSymbolAddress((void**)&w2l, g_w2lo);
    cudaGetSymbolAddress((void**)&w4h, g_w4hi);
    cudaGetSymbolAddress((void**)&w4l, g_w4lo);
    cudaGetSymbolAddress((void**)&w8h, g_w8hi);
    cudaGetSymbolAddress((void**)&w8l, g_w8lo);
    cudaGetSymbolAddress((void**)&p2, g_pre2);
    cudaGetSymbolAddress((void**)&p4, g_pre4);
    cudaGetSymbolAddress((void**)&p8, g_pre8);

    const int sm2g = 2 * (2 * 128 * 128 + 2 * 64 * 128 * 2) + 1024;
    const int sm4g = 2 * (2 * 64 * 128 + 2 * 64 * 128 * 2) + 1024;
    const int sm8g = 2 * (2 * 64 * 128 + 2 * 64 * 64 * 2) + 1024;
    const int smS2 = 4 * (64 * 64 + 4) * 4;     // 65600
    const int smS4 = 4 * (32 * 32 + 4) * 4;
    const int smS8 = 4 * (16 * 16 + 4) * 4;

    static bool s_init = false;
    static cudaStream_t st[3];
    static cudaEvent_t evRoot, evDone[3];
    if (!s_init) {
        for (int i = 0; i < 3; i++)
            cudaStreamCreateWithFlags(&st[i], cudaStreamNonBlocking);
        cudaEventCreateWithFlags(&evRoot, cudaEventDisableTiming);
        for (int i = 0; i < 3; i++)
            cudaEventCreateWithFlags(&evDone[i], cudaEventDisableTiming);
        cudaFuncSetAttribute(sample_split_kernel,
                             cudaFuncAttributeMaxDynamicSharedMemorySize, 66000);
        cudaFuncSetAttribute(gemm_mma_kernel<128, 128>,
                             cudaFuncAttributeMaxDynamicSharedMemorySize, sm2g);
        cudaFuncSetAttribute(gemm_mma_kernel<64, 128>,
                             cudaFuncAttributeMaxDynamicSharedMemorySize, sm4g);
        cudaFuncSetAttribute(gemm_mma_kernel<64, 64>,
                             cudaFuncAttributeMaxDynamicSharedMemorySize, sm8g);
        s_init = true;
    }

    const size_t off_bev2 = 0;
    const size_t off_bev4 = off_bev2 + 2ULL * 256 * 4096;
    const size_t off_bev8 = off_bev4 + 2ULL * 512 * 1024;
    const size_t off_mask = off_bev8 + 2ULL * 1024 * 256;

    // fork from the capture (legacy) stream
    cudaEventRecord(evRoot, 0);
    for (int i = 0; i < 3; i++) cudaStreamWaitEvent(st[i], evRoot, 0);

    // ---- chain 0: scale 2 ----
    precomp_kernel<<<(8 * 16384 + 255) / 256, 256, 0, st[0]>>>(c2, p2, 64, 8 * 16384);
    wsplit_kernel<<<(256 * 1024 + 255) / 256, 256, 0, st[0]>>>(w2, w2h, w2l, 256 * 1024);
    sample_split_kernel<<<dim3(256, BVAL), 256, smS2, st[0]>>>(x3, p2, v2h, v2l, 256, 64, 4096);
    gemm_mma_kernel<128, 128><<<dim3(4096 / 128, 256 / 128, BVAL), 256, sm2g, st[0]>>>(
        w2h, w2l, v2h, v2l, b2, out + off_bev2, 256, 4096, 1024);

    // ---- chain 1: scale 4 ----
    precomp_kernel<<<(8 * 4096 + 255) / 256, 256, 0, st[1]>>>(c4, p4, 32, 8 * 4096);
    wsplit_kernel<<<(512 * 2048 + 255) / 256, 256, 0, st[1]>>>(w4, w4h, w4l, 512 * 2048);
    sample_split_kernel<<<dim3(512, BVAL), 256, smS4, st[1]>>>(x4, p4, v4h, v4l, 512, 32, 1024);
    gemm_mma_kernel<64, 128><<<dim3(1024 / 128, 512 / 64, BVAL), 256, sm4g, st[1]>>>(
        w4h, w4l, v4h, v4l, b4, out + off_bev4, 512, 1024, 2048);

    // ---- chain 2: scale 8 ----
    precomp_kernel<<<(8 * 1024 + 255) / 256, 256, 0, st[2]>>>(c8, p8, 16, 8 * 1024);
    wsplit_kernel<<<(1024 * 4096 + 255) / 256, 256, 0, st[2]>>>(w8, w8h, w8l, 1024 * 4096);
    sample_split_kernel<<<dim3(1024, BVAL), 256, smS8, st[2]>>>(x5, p8, v8h, v8l, 1024, 16, 256);
    gemm_mma_kernel<64, 64><<<dim3(256 / 64, 1024 / 64, BVAL), 256, sm8g, st[2]>>>(
        w8h, w8l, v8h, v8l, b8, out + off_bev8, 1024, 256, 4096);

    // mask on the capture stream (independent)
    mask_kernel<<<(BVAL * 16384 + 255) / 256, 256>>>(c2, out + off_mask, 16384);

    // join all chains back into the capture stream
    for (int i = 0; i < 3; i++) {
        cudaEventRecord(evDone[i], st[i]);
        cudaStreamWaitEvent(0, evDone[i], 0);
    }
}